// round 12
// baseline (speedup 1.0000x reference)
#include <cuda_runtime.h>

#define N_NODES 50000
#define N_EDGES 800000
#define ETOT    (N_EDGES + N_NODES)   // 850000 (self loops appended)
#define C       64
#define NLAYER  3
#define SLOPE   0.2f
#define NSCAN_B 49                    // ceil(50000/1024)

// ---------------- scratch (no allocations allowed) ----------------
__device__ int   g_deg[N_NODES];
__device__ int   g_rowstart[N_NODES];      // shifted convention after scatter:
                                           // row d = [rs[d-1], rs[d]),  rs[-1]=0
__device__ int   g_bsum[64];
__device__ int   g_boff[64];
__device__ int   g_csr_src[ETOT];
__device__ float g_bufA[N_NODES * C];
__device__ float g_bufB[N_NODES * C];
__device__ float g_accum[N_NODES * C];

// ---------------- CSR build ----------------
__global__ void k_reset() {
    int i = blockIdx.x * blockDim.x + threadIdx.x;
    if (i < N_NODES) g_deg[i] = 0;
}

// histogram of real-edge destinations (self loops handled as +1 in scan)
__global__ void k_hist(const int* __restrict__ ei) {
    int t = blockIdx.x * blockDim.x + threadIdx.x;
    if (t >= N_EDGES / 4) return;
    int4 d4 = ((const int4*)(ei + N_EDGES))[t];
    atomicAdd(&g_deg[d4.x], 1);
    atomicAdd(&g_deg[d4.y], 1);
    atomicAdd(&g_deg[d4.z], 1);
    atomicAdd(&g_deg[d4.w], 1);
}

// phase 1: per-block (1024-wide, coalesced) exclusive scan of (deg+1)
__global__ void k_scan1() {
    __shared__ int wsum[32];
    int t = threadIdx.x, b = blockIdx.x;
    int idx = b * 1024 + t;
    int val = (idx < N_NODES) ? (g_deg[idx] + 1) : 0;   // +1 = self loop
    int v = val;
    int lane = t & 31, w = t >> 5;
    #pragma unroll
    for (int o = 1; o < 32; o <<= 1) {
        int u = __shfl_up_sync(0xffffffffu, v, o);
        if (lane >= o) v += u;
    }
    if (lane == 31) wsum[w] = v;
    __syncthreads();
    if (w == 0) {
        int s = wsum[lane];
        #pragma unroll
        for (int o = 1; o < 32; o <<= 1) {
            int u = __shfl_up_sync(0xffffffffu, s, o);
            if (lane >= o) s += u;
        }
        wsum[lane] = s;
    }
    __syncthreads();
    int excl = v - val + (w > 0 ? wsum[w - 1] : 0);
    if (idx < N_NODES) g_rowstart[idx] = excl;
    if (t == 1023) g_bsum[b] = excl + val;
}

// phase 2: scan the 49 block totals
__global__ void k_scan2() {
    __shared__ int sh[64];
    int t = threadIdx.x;
    int v = (t < NSCAN_B) ? g_bsum[t] : 0;
    sh[t] = v;
    __syncthreads();
    for (int o = 1; o < 64; o <<= 1) {
        int u = (t >= o) ? sh[t - o] : 0;
        __syncthreads();
        sh[t] += u;
        __syncthreads();
    }
    if (t < NSCAN_B) g_boff[t] = sh[t] - v;   // exclusive
}

// phase 3: add block offsets
__global__ void k_scan3() {
    int i = blockIdx.x * blockDim.x + threadIdx.x;
    if (i < N_NODES) g_rowstart[i] += g_boff[i >> 10];
}

// scatter: atomicAdd directly on rowstart; afterwards rs[d] == end of row d
__global__ void k_scatter(const int* __restrict__ ei) {
    int e = blockIdx.x * blockDim.x + threadIdx.x;
    if (e >= ETOT) return;
    int s, d;
    if (e < N_EDGES) { s = ei[e]; d = ei[N_EDGES + e]; }
    else             { s = d = e - N_EDGES; }
    int pos = atomicAdd(&g_rowstart[d], 1);
    g_csr_src[pos] = s;
}

// ---------------- fused GAT layer: 16 lanes per node, float4 ----------------
// MODE 0: first layer  (accum  = x + h)
// MODE 1: middle layer (accum += h)
// MODE 2: last layer   (out = (accum + h) * 0.25, no xout store)
template <int MODE>
__global__ void k_layer(const float* __restrict__ xin,
                        const float* __restrict__ attl,
                        const float* __restrict__ biasl,
                        float*       __restrict__ xout,
                        float*       __restrict__ out) {
    int gtid = blockIdx.x * blockDim.x + threadIdx.x;   // exactly 800000 threads
    int node = gtid >> 4;
    int lane = threadIdx.x & 31;
    int fl   = (lane & 15) * 4;                          // feature offset of this lane

    const float4 xd = *(const float4*)(xin  + (size_t)node * C + fl);
    const float4 c0 = *(const float4*)(attl + fl);       // head 0
    const float4 c1 = *(const float4*)(attl + C + fl);   // head 1

    int end = g_rowstart[node];
    int beg = (node > 0) ? g_rowstart[node - 1] : 0;
    int n   = end - beg;
    int n2  = __shfl_xor_sync(0xffffffffu, n, 16);
    int nmax = max(n, n2);

    float  s0 = 0.0f, s1 = 0.0f;
    float4 A0 = make_float4(0.f, 0.f, 0.f, 0.f);
    float4 A1 = make_float4(0.f, 0.f, 0.f, 0.f);

    const int base = lane & 16;                          // first lane of my node group

    for (int t = 0; t < nmax; ++t) {
        bool act = (t < n);
        int  ci  = beg + (act ? t : 0);
        int  src = g_csr_src[ci];                        // group-uniform
        float4 xs = *(const float4*)(xin + (size_t)src * C + fl);

        float m0 = xd.x + xs.x, m1 = xd.y + xs.y;
        float m2 = xd.z + xs.z, m3 = xd.w + xs.w;
        m0 = m0 > 0.f ? m0 : SLOPE * m0;
        m1 = m1 > 0.f ? m1 : SLOPE * m1;
        m2 = m2 > 0.f ? m2 : SLOPE * m2;
        m3 = m3 > 0.f ? m3 : SLOPE * m3;

        float a0p = fmaf(m3, c0.w, fmaf(m2, c0.z, fmaf(m1, c0.y, m0 * c0.x)));
        float a1p = fmaf(m3, c1.w, fmaf(m2, c1.z, fmaf(m1, c1.y, m0 * c1.x)));

        // head-split: bit-3==0 lanes reduce head0, bit-3==1 lanes reduce head1
        float sel = (lane & 8) ? a1p : a0p;
        float oth = (lane & 8) ? a0p : a1p;
        sel += __shfl_xor_sync(0xffffffffu, oth, 8);
        sel += __shfl_xor_sync(0xffffffffu, sel, 4);
        sel += __shfl_xor_sync(0xffffffffu, sel, 2);
        sel += __shfl_xor_sync(0xffffffffu, sel, 1);

        float p  = __expf(sel);                          // unshifted softmax (|alpha| small)
        float p0 = __shfl_sync(0xffffffffu, p, base);
        float p1 = __shfl_sync(0xffffffffu, p, base | 8);

        if (act) {
            s0 += p0;
            s1 += p1;
            A0.x = fmaf(p0, xs.x, A0.x);
            A0.y = fmaf(p0, xs.y, A0.y);
            A0.z = fmaf(p0, xs.z, A0.z);
            A0.w = fmaf(p0, xs.w, A0.w);
            A1.x = fmaf(p1, xs.x, A1.x);
            A1.y = fmaf(p1, xs.y, A1.y);
            A1.z = fmaf(p1, xs.z, A1.z);
            A1.w = fmaf(p1, xs.w, A1.w);
        }
    }

    float inv0 = 0.5f / (s0 + 1e-16f);
    float inv1 = 0.5f / (s1 + 1e-16f);
    float4 bv  = *(const float4*)(biasl + fl);

    float4 o;
    o.x = A0.x * inv0 + A1.x * inv1 + bv.x;
    o.y = A0.y * inv0 + A1.y * inv1 + bv.y;
    o.z = A0.z * inv0 + A1.z * inv1 + bv.z;
    o.w = A0.w * inv0 + A1.w * inv1 + bv.w;

    float4* ap = (float4*)(g_accum + (size_t)node * C + fl);
    if (MODE == 0) {
        *(float4*)(xout + (size_t)node * C + fl) = o;
        float4 av;
        av.x = xd.x + o.x; av.y = xd.y + o.y; av.z = xd.z + o.z; av.w = xd.w + o.w;
        *ap = av;
    } else if (MODE == 1) {
        *(float4*)(xout + (size_t)node * C + fl) = o;
        float4 av = *ap;
        av.x += o.x; av.y += o.y; av.z += o.z; av.w += o.w;
        *ap = av;
    } else {
        float4 av = *ap;
        float4 r;
        r.x = (av.x + o.x) * 0.25f;
        r.y = (av.y + o.y) * 0.25f;
        r.z = (av.z + o.z) * 0.25f;
        r.w = (av.w + o.w) * 0.25f;
        *(float4*)(out + (size_t)node * C + fl) = r;
    }
}

// ---------------- host ----------------
extern "C" void kernel_launch(void* const* d_in, const int* in_sizes, int n_in,
                              void* d_out, int out_size) {
    const float* x    = (const float*)d_in[0];   // [N, C]
    const int*   ei   = (const int*)  d_in[1];   // [2, E]
    const float* att  = (const float*)d_in[2];   // [L, H, C]
    const float* bias = (const float*)d_in[3];   // [L, C]
    float* out = (float*)d_out;

    float *bufA, *bufB;
    cudaGetSymbolAddress((void**)&bufA, g_bufA);
    cudaGetSymbolAddress((void**)&bufB, g_bufB);

    const int T = 256;
    const int gridNode  = (N_NODES + T - 1) / T;          // 196
    const int gridHist  = (N_EDGES / 4 + T - 1) / T;      // 782
    const int gridEdge  = (ETOT + T - 1) / T;             // 3321
    const int gridLayer = (N_NODES * 16) / T;             // 3125 exact

    // CSR build (graph fixed across layers)
    k_reset  <<<gridNode, T>>>();
    k_hist   <<<gridHist, T>>>(ei);
    k_scan1  <<<NSCAN_B, 1024>>>();
    k_scan2  <<<1, 64>>>();
    k_scan3  <<<gridNode, T>>>();
    k_scatter<<<gridEdge, T>>>(ei);

    const float* a0 = att;
    const float* a1 = att + 2 * C;
    const float* a2 = att + 4 * C;

    k_layer<0><<<gridLayer, T>>>(x,    a0, bias,         bufA, out);
    k_layer<1><<<gridLayer, T>>>(bufA, a1, bias + C,     bufB, out);
    k_layer<2><<<gridLayer, T>>>(bufB, a2, bias + 2 * C, nullptr, out);
}

// round 14
// speedup vs baseline: 1.6303x; 1.6303x over previous
#include <cuda_runtime.h>

#define N_NODES 50000
#define N_EDGES 800000
#define ETOT    (N_EDGES + N_NODES)   // 850000 (self loops appended)
#define C       64
#define NLAYER  3
#define SLOPE   0.2f
#define NSCAN_B 49                    // ceil(50000/1024)

// ---------------- scratch (no allocations allowed) ----------------
__device__ int   g_deg[N_NODES];
__device__ int   g_rowstart[N_NODES];      // shifted convention after scatter:
                                           // row d = [rs[d-1], rs[d]),  rs[-1]=0
__device__ int   g_bsum[64];
__device__ int   g_boff[64];
__device__ int   g_csr_src[ETOT];
__device__ float g_bufA[N_NODES * C];
__device__ float g_bufB[N_NODES * C];
__device__ float g_accum[N_NODES * C];

// ---------------- CSR build ----------------
__global__ void k_reset() {
    int i = blockIdx.x * blockDim.x + threadIdx.x;
    if (i < N_NODES) g_deg[i] = 0;
}

// histogram of real-edge destinations (self loops handled as +1 in scan)
__global__ void k_hist(const int* __restrict__ ei) {
    int t = blockIdx.x * blockDim.x + threadIdx.x;
    if (t >= N_EDGES / 4) return;
    int4 d4 = ((const int4*)(ei + N_EDGES))[t];
    atomicAdd(&g_deg[d4.x], 1);
    atomicAdd(&g_deg[d4.y], 1);
    atomicAdd(&g_deg[d4.z], 1);
    atomicAdd(&g_deg[d4.w], 1);
}

// phase 1: per-block (1024-wide, coalesced) exclusive scan of (deg+1)
__global__ void k_scan1() {
    __shared__ int wsum[32];
    int t = threadIdx.x, b = blockIdx.x;
    int idx = b * 1024 + t;
    int val = (idx < N_NODES) ? (g_deg[idx] + 1) : 0;   // +1 = self loop
    int v = val;
    int lane = t & 31, w = t >> 5;
    #pragma unroll
    for (int o = 1; o < 32; o <<= 1) {
        int u = __shfl_up_sync(0xffffffffu, v, o);
        if (lane >= o) v += u;
    }
    if (lane == 31) wsum[w] = v;
    __syncthreads();
    if (w == 0) {
        int s = wsum[lane];
        #pragma unroll
        for (int o = 1; o < 32; o <<= 1) {
            int u = __shfl_up_sync(0xffffffffu, s, o);
            if (lane >= o) s += u;
        }
        wsum[lane] = s;
    }
    __syncthreads();
    int excl = v - val + (w > 0 ? wsum[w - 1] : 0);
    if (idx < N_NODES) g_rowstart[idx] = excl;
    if (t == 1023) g_bsum[b] = excl + val;
}

// phase 2: scan the 49 block totals
__global__ void k_scan2() {
    __shared__ int sh[64];
    int t = threadIdx.x;
    int v = (t < NSCAN_B) ? g_bsum[t] : 0;
    sh[t] = v;
    __syncthreads();
    for (int o = 1; o < 64; o <<= 1) {
        int u = (t >= o) ? sh[t - o] : 0;
        __syncthreads();
        sh[t] += u;
        __syncthreads();
    }
    if (t < NSCAN_B) g_boff[t] = sh[t] - v;   // exclusive
}

// phase 3: add block offsets
__global__ void k_scan3() {
    int i = blockIdx.x * blockDim.x + threadIdx.x;
    if (i < N_NODES) g_rowstart[i] += g_boff[i >> 10];
}

// scatter: atomicAdd directly on rowstart; afterwards rs[d] == end of row d
__global__ void k_scatter(const int* __restrict__ ei) {
    int e = blockIdx.x * blockDim.x + threadIdx.x;
    if (e >= ETOT) return;
    int s, d;
    if (e < N_EDGES) { s = ei[e]; d = ei[N_EDGES + e]; }
    else             { s = d = e - N_EDGES; }
    int pos = atomicAdd(&g_rowstart[d], 1);
    g_csr_src[pos] = s;
}

// ---------------- fused GAT layer: one WARP per node, float2/lane ----------
// MODE 0: first layer  (accum  = x + h)
// MODE 1: middle layer (accum += h)
// MODE 2: last layer   (out = (accum + h) * 0.25, no xout store)
template <int MODE>
__global__ void k_layer(const float* __restrict__ xin,
                        const float* __restrict__ attl,
                        const float* __restrict__ biasl,
                        float*       __restrict__ xout,
                        float*       __restrict__ out) {
    const unsigned FULL = 0xffffffffu;
    int gtid = blockIdx.x * blockDim.x + threadIdx.x;
    int node = gtid >> 5;
    int lane = threadIdx.x & 31;
    if (node >= N_NODES) return;

    const float2 xd = *(const float2*)(xin  + (size_t)node * C + lane * 2);
    const float2 c0 = *(const float2*)(attl + lane * 2);       // head 0
    const float2 c1 = *(const float2*)(attl + C + lane * 2);   // head 1

    int end = g_rowstart[node];
    int beg = (node > 0) ? g_rowstart[node - 1] : 0;

    float  s0 = 0.0f, s1 = 0.0f;
    float2 A0 = make_float2(0.f, 0.f);
    float2 A1 = make_float2(0.f, 0.f);

    // process edges in chunks of 32: coalesced index load, shuffle-distributed
    for (int cb = beg; cb < end; cb += 32) {
        int idx = cb + lane;
        int my  = (idx < end) ? g_csr_src[idx] : 0;
        int cnt = min(32, end - cb);

        #pragma unroll 4
        for (int t = 0; t < cnt; ++t) {
            int src = __shfl_sync(FULL, my, t);
            float2 xs = *(const float2*)(xin + (size_t)src * C + lane * 2);

            float mx = xd.x + xs.x;
            float mw = xd.y + xs.y;
            mx = mx > 0.f ? mx : SLOPE * mx;
            mw = mw > 0.f ? mw : SLOPE * mw;

            float a0p = fmaf(mw, c0.y, mx * c0.x);
            float a1p = fmaf(mw, c1.y, mx * c1.x);

            // head-split: lanes 0-15 reduce head0, 16-31 reduce head1
            float sel = (lane & 16) ? a1p : a0p;
            float oth = (lane & 16) ? a0p : a1p;
            sel += __shfl_xor_sync(FULL, oth, 16);
            sel += __shfl_xor_sync(FULL, sel, 8);
            sel += __shfl_xor_sync(FULL, sel, 4);
            sel += __shfl_xor_sync(FULL, sel, 2);
            sel += __shfl_xor_sync(FULL, sel, 1);

            float p  = __expf(sel);                  // unshifted softmax: |alpha| small
            float p0 = __shfl_sync(FULL, p, 0);
            float p1 = __shfl_sync(FULL, p, 16);

            s0 += p0;
            s1 += p1;
            A0.x = fmaf(p0, xs.x, A0.x);
            A0.y = fmaf(p0, xs.y, A0.y);
            A1.x = fmaf(p1, xs.x, A1.x);
            A1.y = fmaf(p1, xs.y, A1.y);
        }
    }

    float inv0 = 0.5f / (s0 + 1e-16f);
    float inv1 = 0.5f / (s1 + 1e-16f);
    float2 bv  = *(const float2*)(biasl + lane * 2);

    float2 o;
    o.x = A0.x * inv0 + A1.x * inv1 + bv.x;
    o.y = A0.y * inv0 + A1.y * inv1 + bv.y;

    float2* ap = (float2*)(g_accum + (size_t)node * C + lane * 2);
    if (MODE == 0) {
        *(float2*)(xout + (size_t)node * C + lane * 2) = o;
        *ap = make_float2(xd.x + o.x, xd.y + o.y);
    } else if (MODE == 1) {
        *(float2*)(xout + (size_t)node * C + lane * 2) = o;
        float2 av = *ap;
        av.x += o.x;
        av.y += o.y;
        *ap = av;
    } else {
        float2 av = *ap;
        float2 r;
        r.x = (av.x + o.x) * 0.25f;
        r.y = (av.y + o.y) * 0.25f;
        *(float2*)(out + (size_t)node * C + lane * 2) = r;
    }
}

// ---------------- host ----------------
extern "C" void kernel_launch(void* const* d_in, const int* in_sizes, int n_in,
                              void* d_out, int out_size) {
    const float* x    = (const float*)d_in[0];   // [N, C]
    const int*   ei   = (const int*)  d_in[1];   // [2, E]
    const float* att  = (const float*)d_in[2];   // [L, H, C]
    const float* bias = (const float*)d_in[3];   // [L, C]
    float* out = (float*)d_out;

    float *bufA, *bufB;
    cudaGetSymbolAddress((void**)&bufA, g_bufA);
    cudaGetSymbolAddress((void**)&bufB, g_bufB);

    const int T = 256;
    const int gridNode  = (N_NODES + T - 1) / T;          // 196
    const int gridHist  = (N_EDGES / 4 + T - 1) / T;      // 782
    const int gridEdge  = (ETOT + T - 1) / T;             // 3321
    const int gridLayer = (N_NODES * 32 + T - 1) / T;     // 6250

    // CSR build (graph fixed across layers)
    k_reset  <<<gridNode, T>>>();
    k_hist   <<<gridHist, T>>>(ei);
    k_scan1  <<<NSCAN_B, 1024>>>();
    k_scan2  <<<1, 64>>>();
    k_scan3  <<<gridNode, T>>>();
    k_scatter<<<gridEdge, T>>>(ei);

    k_layer<0><<<gridLayer, T>>>(x,    att,         bias,         bufA, out);
    k_layer<1><<<gridLayer, T>>>(bufA, att + 2 * C, bias + C,     bufB, out);
    k_layer<2><<<gridLayer, T>>>(bufB, att + 4 * C, bias + 2 * C, nullptr, out);
}

// round 15
// speedup vs baseline: 1.7433x; 1.0693x over previous
#include <cuda_runtime.h>

#define N_NODES 50000
#define N_EDGES 800000
#define ETOT    (N_EDGES + N_NODES)   // 850000 (self loops appended)
#define C       64
#define NLAYER  3
#define SLOPE   0.2f
#define NSCAN_B 49                    // ceil(50000/1024)

// ---------------- scratch (no allocations allowed) ----------------
__device__ int   g_deg[N_NODES];
__device__ int   g_rowstart[N_NODES];      // shifted convention after scatter:
                                           // row d = [rs[d-1], rs[d]),  rs[-1]=0
__device__ int   g_bsum[64];
__device__ int   g_csr_src[ETOT];
__device__ float g_bufA[N_NODES * C];
__device__ float g_bufB[N_NODES * C];
__device__ float g_accum[N_NODES * C];

// ---------------- CSR build ----------------

// histogram of real-edge destinations (self loops handled as +1 in scan)
__global__ void k_hist(const int* __restrict__ ei) {
    int t = blockIdx.x * blockDim.x + threadIdx.x;
    if (t >= N_EDGES / 4) return;
    int4 d4 = ((const int4*)(ei + N_EDGES))[t];
    atomicAdd(&g_deg[d4.x], 1);
    atomicAdd(&g_deg[d4.y], 1);
    atomicAdd(&g_deg[d4.z], 1);
    atomicAdd(&g_deg[d4.w], 1);
}

// phase 1: per-block (1024-wide, coalesced) exclusive scan of (deg+1)
__global__ void k_scan1() {
    __shared__ int wsum[32];
    int t = threadIdx.x, b = blockIdx.x;
    int idx = b * 1024 + t;
    int val = (idx < N_NODES) ? (g_deg[idx] + 1) : 0;   // +1 = self loop
    int v = val;
    int lane = t & 31, w = t >> 5;
    #pragma unroll
    for (int o = 1; o < 32; o <<= 1) {
        int u = __shfl_up_sync(0xffffffffu, v, o);
        if (lane >= o) v += u;
    }
    if (lane == 31) wsum[w] = v;
    __syncthreads();
    if (w == 0) {
        int s = wsum[lane];
        #pragma unroll
        for (int o = 1; o < 32; o <<= 1) {
            int u = __shfl_up_sync(0xffffffffu, s, o);
            if (lane >= o) s += u;
        }
        wsum[lane] = s;
    }
    __syncthreads();
    int excl = v - val + (w > 0 ? wsum[w - 1] : 0);
    if (idx < N_NODES) g_rowstart[idx] = excl;
    if (t == 1023) g_bsum[b] = excl + val;
}

// phase 2+3 fused: each block recomputes the (tiny) block-total prefix it
// needs from g_bsum, then adds it to its 256 rowstart entries.
// Every 256-node block lies inside one 1024-chunk, so one offset per block.
__global__ void k_scanfix() {
    __shared__ int off;
    int b  = blockIdx.x;
    int cb = b >> 2;                       // this block's 1024-chunk index
    if (threadIdx.x < 32) {
        int lane = threadIdx.x;
        int v = (lane < cb) ? g_bsum[lane] : 0;
        if (lane + 32 < cb) v += g_bsum[lane + 32];
        #pragma unroll
        for (int o = 16; o; o >>= 1) v += __shfl_xor_sync(0xffffffffu, v, o);
        if (lane == 0) off = v;
    }
    __syncthreads();
    int i = b * 256 + threadIdx.x;
    if (i < N_NODES) g_rowstart[i] += off;
}

// scatter: atomicAdd directly on rowstart; afterwards rs[d] == end of row d
__global__ void k_scatter(const int* __restrict__ ei) {
    int e = blockIdx.x * blockDim.x + threadIdx.x;
    if (e >= ETOT) return;
    int s, d;
    if (e < N_EDGES) { s = ei[e]; d = ei[N_EDGES + e]; }
    else             { s = d = e - N_EDGES; }
    int pos = atomicAdd(&g_rowstart[d], 1);
    g_csr_src[pos] = s;
}

// ---------------- fused GAT layer: one WARP per node, float2/lane ----------
// MODE 0: first layer  (accum  = x + h)
// MODE 1: middle layer (accum += h)
// MODE 2: last layer   (out = (accum + h) * 0.25, no xout store)
template <int MODE>
__global__ void k_layer(const float* __restrict__ xin,
                        const float* __restrict__ attl,
                        const float* __restrict__ biasl,
                        float*       __restrict__ xout,
                        float*       __restrict__ out) {
    const unsigned FULL = 0xffffffffu;
    int gtid = blockIdx.x * blockDim.x + threadIdx.x;
    int node = gtid >> 5;
    int lane = threadIdx.x & 31;
    if (node >= N_NODES) return;

    const float2 xd = *(const float2*)(xin  + (size_t)node * C + lane * 2);
    const float2 c0 = *(const float2*)(attl + lane * 2);       // head 0
    const float2 c1 = *(const float2*)(attl + C + lane * 2);   // head 1

    int end = g_rowstart[node];
    int beg = (node > 0) ? g_rowstart[node - 1] : 0;

    float  s0 = 0.0f, s1 = 0.0f;
    float2 A0 = make_float2(0.f, 0.f);
    float2 A1 = make_float2(0.f, 0.f);

    const bool hi = (lane & 16) != 0;      // head-1 half of the warp

    // process edges in chunks of 32: coalesced index load, shuffle-distributed,
    // two independent edge chains per iteration for latency overlap
    for (int cb = beg; cb < end; cb += 32) {
        int idx = cb + lane;
        int my  = (idx < end) ? g_csr_src[idx] : 0;
        int cnt = min(32, end - cb);

        int t = 0;
        for (; t + 2 <= cnt; t += 2) {
            int srcA = __shfl_sync(FULL, my, t);
            int srcB = __shfl_sync(FULL, my, t + 1);
            float2 xA = *(const float2*)(xin + (size_t)srcA * C + lane * 2);
            float2 xB = *(const float2*)(xin + (size_t)srcB * C + lane * 2);

            float mAx = xd.x + xA.x, mAy = xd.y + xA.y;
            float mBx = xd.x + xB.x, mBy = xd.y + xB.y;
            mAx = mAx > 0.f ? mAx : SLOPE * mAx;
            mAy = mAy > 0.f ? mAy : SLOPE * mAy;
            mBx = mBx > 0.f ? mBx : SLOPE * mBx;
            mBy = mBy > 0.f ? mBy : SLOPE * mBy;

            float a0A = fmaf(mAy, c0.y, mAx * c0.x);
            float a1A = fmaf(mAy, c1.y, mAx * c1.x);
            float a0B = fmaf(mBy, c0.y, mBx * c0.x);
            float a1B = fmaf(mBy, c1.y, mBx * c1.x);

            // head-split reduce, two chains interleaved
            float selA = hi ? a1A : a0A,  othA = hi ? a0A : a1A;
            float selB = hi ? a1B : a0B,  othB = hi ? a0B : a1B;
            selA += __shfl_xor_sync(FULL, othA, 16);
            selB += __shfl_xor_sync(FULL, othB, 16);
            selA += __shfl_xor_sync(FULL, selA, 8);
            selB += __shfl_xor_sync(FULL, selB, 8);
            selA += __shfl_xor_sync(FULL, selA, 4);
            selB += __shfl_xor_sync(FULL, selB, 4);
            selA += __shfl_xor_sync(FULL, selA, 2);
            selB += __shfl_xor_sync(FULL, selB, 2);
            selA += __shfl_xor_sync(FULL, selA, 1);
            selB += __shfl_xor_sync(FULL, selB, 1);

            float pA = __expf(selA);                 // own half's softmax numer
            float pB = __expf(selB);
            float qA = __shfl_xor_sync(FULL, pA, 16); // other half's
            float qB = __shfl_xor_sync(FULL, pB, 16);

            float p0A = hi ? qA : pA,  p1A = hi ? pA : qA;
            float p0B = hi ? qB : pB,  p1B = hi ? pB : qB;

            s0 += p0A + p0B;
            s1 += p1A + p1B;
            A0.x = fmaf(p0A, xA.x, fmaf(p0B, xB.x, A0.x));
            A0.y = fmaf(p0A, xA.y, fmaf(p0B, xB.y, A0.y));
            A1.x = fmaf(p1A, xA.x, fmaf(p1B, xB.x, A1.x));
            A1.y = fmaf(p1A, xA.y, fmaf(p1B, xB.y, A1.y));
        }

        if (t < cnt) {                               // odd tail
            int src = __shfl_sync(FULL, my, t);
            float2 xs = *(const float2*)(xin + (size_t)src * C + lane * 2);

            float mx = xd.x + xs.x, mw = xd.y + xs.y;
            mx = mx > 0.f ? mx : SLOPE * mx;
            mw = mw > 0.f ? mw : SLOPE * mw;

            float a0p = fmaf(mw, c0.y, mx * c0.x);
            float a1p = fmaf(mw, c1.y, mx * c1.x);

            float sel = hi ? a1p : a0p,  oth = hi ? a0p : a1p;
            sel += __shfl_xor_sync(FULL, oth, 16);
            sel += __shfl_xor_sync(FULL, sel, 8);
            sel += __shfl_xor_sync(FULL, sel, 4);
            sel += __shfl_xor_sync(FULL, sel, 2);
            sel += __shfl_xor_sync(FULL, sel, 1);

            float p = __expf(sel);
            float q = __shfl_xor_sync(FULL, p, 16);
            float p0 = hi ? q : p,  p1 = hi ? p : q;

            s0 += p0;
            s1 += p1;
            A0.x = fmaf(p0, xs.x, A0.x);
            A0.y = fmaf(p0, xs.y, A0.y);
            A1.x = fmaf(p1, xs.x, A1.x);
            A1.y = fmaf(p1, xs.y, A1.y);
        }
    }

    float inv0 = 0.5f / (s0 + 1e-16f);
    float inv1 = 0.5f / (s1 + 1e-16f);
    float2 bv  = *(const float2*)(biasl + lane * 2);

    float2 o;
    o.x = A0.x * inv0 + A1.x * inv1 + bv.x;
    o.y = A0.y * inv0 + A1.y * inv1 + bv.y;

    float2* ap = (float2*)(g_accum + (size_t)node * C + lane * 2);
    if (MODE == 0) {
        *(float2*)(xout + (size_t)node * C + lane * 2) = o;
        *ap = make_float2(xd.x + o.x, xd.y + o.y);
    } else if (MODE == 1) {
        *(float2*)(xout + (size_t)node * C + lane * 2) = o;
        float2 av = *ap;
        av.x += o.x;
        av.y += o.y;
        *ap = av;
    } else {
        float2 av = *ap;
        float2 r;
        r.x = (av.x + o.x) * 0.25f;
        r.y = (av.y + o.y) * 0.25f;
        *(float2*)(out + (size_t)node * C + lane * 2) = r;
    }
}

// ---------------- host ----------------
extern "C" void kernel_launch(void* const* d_in, const int* in_sizes, int n_in,
                              void* d_out, int out_size) {
    const float* x    = (const float*)d_in[0];   // [N, C]
    const int*   ei   = (const int*)  d_in[1];   // [2, E]
    const float* att  = (const float*)d_in[2];   // [L, H, C]
    const float* bias = (const float*)d_in[3];   // [L, C]
    float* out = (float*)d_out;

    float *bufA, *bufB;
    int   *degp;
    cudaGetSymbolAddress((void**)&bufA, g_bufA);
    cudaGetSymbolAddress((void**)&bufB, g_bufB);
    cudaGetSymbolAddress((void**)&degp, g_deg);

    const int T = 256;
    const int gridNode  = (N_NODES + T - 1) / T;          // 196
    const int gridHist  = (N_EDGES / 4 + T - 1) / T;      // 782
    const int gridEdge  = (ETOT + T - 1) / T;             // 3321
    const int gridLayer = (N_NODES * 32 + T - 1) / T;     // 6250

    // CSR build (graph fixed across layers)
    cudaMemsetAsync(degp, 0, N_NODES * sizeof(int));
    k_hist   <<<gridHist, T>>>(ei);
    k_scan1  <<<NSCAN_B, 1024>>>();
    k_scanfix<<<gridNode, T>>>();
    k_scatter<<<gridEdge, T>>>(ei);

    k_layer<0><<<gridLayer, T>>>(x,    att,         bias,         bufA, out);
    k_layer<1><<<gridLayer, T>>>(bufA, att + 2 * C, bias + C,     bufB, out);
    k_layer<2><<<gridLayer, T>>>(bufB, att + 4 * C, bias + 2 * C, nullptr, out);
}